// round 5
// baseline (speedup 1.0000x reference)
#include <cuda_runtime.h>
#include <cstdint>

// Problem shape (fixed): x[B=4,S=4096,H=1024], conv_w[L=20,H,H], norm_w[H]
#define H_DIM   1024
#define L_DIM   20
#define M_TOTAL 16384   // B*S
#define K_DIM   1024
#define N_DIM   1024
#define EPS     1e-6f

#define BM 128
#define BN 256
#define BK 32
#define KT (K_DIM / BK)          // 32 k-tiles
#define NTHREADS 512
// floats per stage: A 128*32 + B 256*32 = 12288 ; 2 stages = 24576 floats = 96 KB
#define STAGE_FLOATS 12288
#define SMEM_BYTES (2 * STAGE_FLOATS * 4)

// Scratch: averaged weight matrix W[o][i] (tf32-rounded), 4 MB — L2-resident.
__device__ float g_W[H_DIM * H_DIM];

__device__ __forceinline__ float f2tf32f(float f) {
    uint32_t r;
    asm("cvt.rna.tf32.f32 %0, %1;" : "=r"(r) : "f"(f));
    return __uint_as_float(r);
}

// ---------------------------------------------------------------------------
// Kernel 1: W[o,i] = (1/L) * sum_l conv_w[l,o,i], rounded to tf32.
// ---------------------------------------------------------------------------
__global__ void reduce_w_kernel(const float* __restrict__ conv_w) {
    int idx = (blockIdx.x * blockDim.x + threadIdx.x) * 4;
    const float inv = 1.0f / (float)L_DIM;
    float4 acc = make_float4(0.f, 0.f, 0.f, 0.f);
#pragma unroll
    for (int l = 0; l < L_DIM; l++) {
        float4 v = *(const float4*)(conv_w + (size_t)l * H_DIM * H_DIM + idx);
        acc.x += v.x; acc.y += v.y; acc.z += v.z; acc.w += v.w;
    }
    float4 o;
    o.x = f2tf32f(acc.x * inv);
    o.y = f2tf32f(acc.y * inv);
    o.z = f2tf32f(acc.z * inv);
    o.w = f2tf32f(acc.w * inv);
    *(float4*)(g_W + idx) = o;
}

// ---------------------------------------------------------------------------
// Kernel 2: y[m,n] = sum_k x[m,k] * W[n,k]  — TF32 mma.sync, fp32 accum.
// CTA 128x256x32, 16 warps in 4(m) x 4(n), warp tile 32x64.
// 2-stage smem double buffer + register-staged global prefetch (1 sync/iter).
// XOR-swizzled smem: float4 col' = col4 ^ (row & 7)  -> conflict-free
// fragment reads (bank = (kk+tg) ^ (g<<2) covers all 32 banks).
// ---------------------------------------------------------------------------
__global__ __launch_bounds__(NTHREADS, 1)
void gemm_tf32_kernel(const float* __restrict__ x, float* __restrict__ y) {
    extern __shared__ float smem[];

    const int tid  = threadIdx.x;
    const int warp = tid >> 5;
    const int lane = tid & 31;
    const int wm   = warp & 3;    // 0..3 -> m offset wm*32
    const int wn   = warp >> 2;   // 0..3 -> n offset wn*64
    const int g    = lane >> 2;   // 0..7
    const int tg   = lane & 3;    // 0..3

    const int bm = blockIdx.y * BM;
    const int bn = blockIdx.x * BN;

    float acc[2][8][4];
#pragma unroll
    for (int mi = 0; mi < 2; mi++)
#pragma unroll
        for (int ni = 0; ni < 8; ni++)
#pragma unroll
            for (int c = 0; c < 4; c++) acc[mi][ni][c] = 0.f;

    float4 ra[2], rb[4];

    // ---- global -> regs (tile kt) ----
    auto ldg = [&](int kt) {
        const int k0 = kt * BK;
#pragma unroll
        for (int i = 0; i < 2; i++) {
            int idx = tid + i * NTHREADS;           // 0..1023
            int row = idx >> 3, c4 = idx & 7;
            ra[i] = *(const float4*)(x + (size_t)(bm + row) * K_DIM + k0 + c4 * 4);
        }
#pragma unroll
        for (int i = 0; i < 4; i++) {
            int idx = tid + i * NTHREADS;           // 0..2047
            int row = idx >> 3, c4 = idx & 7;
            rb[i] = *(const float4*)(g_W + (size_t)(bn + row) * K_DIM + k0 + c4 * 4);
        }
    };

    // ---- regs -> smem stage s (x rounded to tf32 here; W pre-rounded) ----
    auto sts = [&](int s) {
        float* As = smem + s * STAGE_FLOATS;
        float* Bs = As + BM * BK;
#pragma unroll
        for (int i = 0; i < 2; i++) {
            int idx = tid + i * NTHREADS;
            int row = idx >> 3, c4 = idx & 7;
            float4 v = ra[i];
            v.x = f2tf32f(v.x); v.y = f2tf32f(v.y);
            v.z = f2tf32f(v.z); v.w = f2tf32f(v.w);
            *(float4*)(As + row * BK + (c4 ^ (row & 7)) * 4) = v;
        }
#pragma unroll
        for (int i = 0; i < 4; i++) {
            int idx = tid + i * NTHREADS;
            int row = idx >> 3, c4 = idx & 7;
            *(float4*)(Bs + row * BK + (c4 ^ (row & 7)) * 4) = rb[i];
        }
    };

    // ---- compute one 32-K tile from stage s ----
    auto compute = [&](int s) {
        const float* As = smem + s * STAGE_FLOATS;
        const float* Bs = As + BM * BK;
#pragma unroll
        for (int kk = 0; kk < BK; kk += 8) {
            const int off0 = (kk + tg) ^ (g << 2);
            const int off1 = (kk + tg + 4) ^ (g << 2);
            uint32_t a[2][4];
#pragma unroll
            for (int mi = 0; mi < 2; mi++) {
                const int r0 = (wm * 32 + mi * 16 + g) * BK;
                const int r1 = r0 + 8 * BK;
                a[mi][0] = __float_as_uint(As[r0 + off0]);
                a[mi][1] = __float_as_uint(As[r1 + off0]);
                a[mi][2] = __float_as_uint(As[r0 + off1]);
                a[mi][3] = __float_as_uint(As[r1 + off1]);
            }
#pragma unroll
            for (int ni = 0; ni < 8; ni++) {
                const int br = (wn * 64 + ni * 8 + g) * BK;
                uint32_t b0 = __float_as_uint(Bs[br + off0]);
                uint32_t b1 = __float_as_uint(Bs[br + off1]);
#pragma unroll
                for (int mi = 0; mi < 2; mi++)
                    asm volatile(
                        "mma.sync.aligned.m16n8k8.row.col.f32.tf32.tf32.f32 "
                        "{%0,%1,%2,%3}, {%4,%5,%6,%7}, {%8,%9}, {%0,%1,%2,%3};"
                        : "+f"(acc[mi][ni][0]), "+f"(acc[mi][ni][1]),
                          "+f"(acc[mi][ni][2]), "+f"(acc[mi][ni][3])
                        : "r"(a[mi][0]), "r"(a[mi][1]), "r"(a[mi][2]), "r"(a[mi][3]),
                          "r"(b0), "r"(b1));
            }
        }
    };

    // ---- pipelined mainloop: 1 syncthreads per K-tile ----
    ldg(0);
    sts(0);
    ldg(1);
    __syncthreads();
#pragma unroll 1
    for (int t = 0; t < KT; t++) {
        const int cur = t & 1;
        if (t + 1 < KT) sts(cur ^ 1);       // store tile t+1 (regs) -> other stage
        if (t + 2 < KT) ldg(t + 2);         // prefetch tile t+2 -> regs
        compute(cur);
        __syncthreads();
    }

    // ---- epilogue ----
#pragma unroll
    for (int mi = 0; mi < 2; mi++) {
#pragma unroll
        for (int ni = 0; ni < 8; ni++) {
            const int row = bm + wm * 32 + mi * 16 + g;
            const int col = bn + wn * 64 + ni * 8 + tg * 2;
            *(float2*)(y + (size_t)row       * N_DIM + col) =
                make_float2(acc[mi][ni][0], acc[mi][ni][1]);
            *(float2*)(y + (size_t)(row + 8) * N_DIM + col) =
                make_float2(acc[mi][ni][2], acc[mi][ni][3]);
        }
    }
}

// ---------------------------------------------------------------------------
// Kernel 3: in-place RMSNorm over rows of 1024, times norm_w.
// ---------------------------------------------------------------------------
__global__ void rmsnorm_kernel(float* __restrict__ y, const float* __restrict__ nw) {
    __shared__ float red[8];
    const int row = blockIdx.x;
    const int tid = threadIdx.x;
    float4* p = (float4*)(y + (size_t)row * H_DIM);

    float4 v = p[tid];
    float ss = v.x * v.x + v.y * v.y + v.z * v.z + v.w * v.w;
#pragma unroll
    for (int o = 16; o; o >>= 1) ss += __shfl_xor_sync(0xFFFFFFFFu, ss, o);
    if ((tid & 31) == 0) red[tid >> 5] = ss;
    __syncthreads();
    if (tid < 32) {
        float s = (tid < 8) ? red[tid] : 0.f;
#pragma unroll
        for (int o = 4; o; o >>= 1) s += __shfl_xor_sync(0xFFFFFFFFu, s, o);
        if (tid == 0) red[0] = s;
    }
    __syncthreads();

    const float scale = rsqrtf(red[0] * (1.0f / H_DIM) + EPS);
    float4 w = ((const float4*)nw)[tid];
    v.x *= scale * w.x;
    v.y *= scale * w.y;
    v.z *= scale * w.z;
    v.w *= scale * w.w;
    p[tid] = v;
}

// ---------------------------------------------------------------------------
extern "C" void kernel_launch(void* const* d_in, const int* in_sizes, int n_in,
                              void* d_out, int out_size) {
    const float* x      = (const float*)d_in[0];
    const float* conv_w = (const float*)d_in[1];
    const float* norm_w = (const float*)d_in[2];
    float* out = (float*)d_out;

    // 96 KB dynamic smem for the GEMM (sticky attribute; idempotent per call)
    cudaFuncSetAttribute(gemm_tf32_kernel,
                         cudaFuncAttributeMaxDynamicSharedMemorySize, SMEM_BYTES);

    reduce_w_kernel<<<(H_DIM * H_DIM) / (256 * 4), 256>>>(conv_w);

    dim3 grid(N_DIM / BN, M_TOTAL / BM);   // 4 x 128 = 512 CTAs
    gemm_tf32_kernel<<<grid, NTHREADS, SMEM_BYTES>>>(x, out);

    rmsnorm_kernel<<<M_TOTAL, 256>>>(out, norm_w);
}

// round 7
// speedup vs baseline: 2.0041x; 2.0041x over previous
#include <cuda_runtime.h>
#include <cuda_fp16.h>
#include <cstdint>

// Problem shape (fixed): x[B=4,S=4096,H=1024], conv_w[L=20,H,H], norm_w[H]
#define H_DIM   1024
#define L_DIM   20
#define M_TOTAL 16384
#define K_DIM   1024
#define N_DIM   1024
#define EPS     1e-6f

// ---- GEMM config ----
#define BM 128
#define BN 256
#define BKH 64                      // K-tile in halfs (128 B/row)
#define KTILES (K_DIM / BKH)        // 16
#define STAGES 4
#define A_STAGE_BYTES (BM * 128)    // 16384
#define B_STAGE_BYTES (BN * 128)    // 32768
#define STAGE_BYTES (A_STAGE_BYTES + B_STAGE_BYTES)   // 49152
#define SMEM_BYTES (STAGES * STAGE_BYTES)             // 196608
#define NTHREADS 256

// fp16 scratch (device globals — allocation-free)
__device__ __half g_Wh[N_DIM * K_DIM];        // 2 MB, averaged + rounded
__device__ __half g_Xh[(size_t)M_TOTAL * K_DIM]; // 32 MB

// ---------------------------------------------------------------------------
// Kernel 1: W[o,i] = (1/L) * sum_l conv_w[l,o,i]  -> fp16
// ---------------------------------------------------------------------------
__global__ void prep_w_kernel(const float* __restrict__ conv_w) {
    int idx = (blockIdx.x * blockDim.x + threadIdx.x) * 4;
    const float inv = 1.0f / (float)L_DIM;
    float4 acc = make_float4(0.f, 0.f, 0.f, 0.f);
#pragma unroll
    for (int l = 0; l < L_DIM; l++) {
        float4 v = *(const float4*)(conv_w + (size_t)l * H_DIM * H_DIM + idx);
        acc.x += v.x; acc.y += v.y; acc.z += v.z; acc.w += v.w;
    }
    __half2 h0 = __floats2half2_rn(acc.x * inv, acc.y * inv);
    __half2 h1 = __floats2half2_rn(acc.z * inv, acc.w * inv);
    uint2 o = make_uint2(*(uint32_t*)&h0, *(uint32_t*)&h1);
    *(uint2*)(g_Wh + idx) = o;
}

// ---------------------------------------------------------------------------
// Kernel 2: x (fp32) -> g_Xh (fp16)
// ---------------------------------------------------------------------------
__global__ void prep_x_kernel(const float* __restrict__ x) {
    size_t idx = ((size_t)blockIdx.x * blockDim.x + threadIdx.x) * 4;
    float4 v = *(const float4*)(x + idx);
    __half2 h0 = __floats2half2_rn(v.x, v.y);
    __half2 h1 = __floats2half2_rn(v.z, v.w);
    *(uint2*)(g_Xh + idx) = make_uint2(*(uint32_t*)&h0, *(uint32_t*)&h1);
}

// ---------------------------------------------------------------------------
// Kernel 3: y = x @ W^T  (fp16 mma.sync m16n8k16, fp32 accum)
// CTA 128x256xK64, 256 thr, 8 warps = 2(m) x 4(n), warp tile 64x64.
// 4-stage cp.async pipeline, SW128 swizzle, ldmatrix.x4 fragment loads.
// ---------------------------------------------------------------------------
__device__ __forceinline__ uint32_t smem_u32(const void* p) {
    uint32_t a;
    asm("{ .reg .u64 t; cvta.to.shared.u64 t, %1; cvt.u32.u64 %0, t; }" : "=r"(a) : "l"(p));
    return a;
}
__device__ __forceinline__ void ldsm_x4(uint32_t& r0, uint32_t& r1, uint32_t& r2, uint32_t& r3,
                                        uint32_t addr) {
    asm volatile("ldmatrix.sync.aligned.m8n8.x4.shared.b16 {%0,%1,%2,%3}, [%4];"
                 : "=r"(r0), "=r"(r1), "=r"(r2), "=r"(r3) : "r"(addr));
}

__global__ __launch_bounds__(NTHREADS, 1)
void gemm_f16_kernel(float* __restrict__ y) {
    extern __shared__ char smem[];
    const uint32_t sbase = smem_u32(smem);

    const int tid  = threadIdx.x;
    const int warp = tid >> 5;
    const int lane = tid & 31;
    const int wm   = warp >> 2;          // 0..1 -> m offset wm*64
    const int wn   = warp & 3;           // 0..3 -> n offset wn*64
    const int g    = lane >> 2;          // 0..7
    const int tg   = lane & 3;           // 0..3
    const int quad = lane >> 3;          // 0..3 (ldmatrix octet)
    const int lrow = lane & 7;

    const int bm = blockIdx.y * BM;
    const int bn = blockIdx.x * BN;

    float acc[4][8][4];
#pragma unroll
    for (int mi = 0; mi < 4; mi++)
#pragma unroll
        for (int ni = 0; ni < 8; ni++)
#pragma unroll
            for (int c = 0; c < 4; c++) acc[mi][ni][c] = 0.f;

    // ---- cp.async one K-tile into stage s ----
    auto load_tile = [&](int s, int t) {
        const uint32_t ab = sbase + s * STAGE_BYTES;
        const uint32_t bb = ab + A_STAGE_BYTES;
        const int k0 = t * BKH;
        // A: 1024 x 16B chunks (128 rows x 8 chunks) -> 4 per thread
#pragma unroll
        for (int i = 0; i < 4; i++) {
            const int id = tid + i * NTHREADS;
            const int row = id >> 3, c = id & 7;
            const uint32_t dst = ab + ((row << 3) + (c ^ (row & 7))) * 16;
            const __half* src = g_Xh + (size_t)(bm + row) * K_DIM + k0 + c * 8;
            asm volatile("cp.async.cg.shared.global [%0], [%1], 16;"
                         :: "r"(dst), "l"(src) : "memory");
        }
        // B: 2048 chunks (256 rows x 8) -> 8 per thread
#pragma unroll
        for (int i = 0; i < 8; i++) {
            const int id = tid + i * NTHREADS;
            const int row = id >> 3, c = id & 7;
            const uint32_t dst = bb + ((row << 3) + (c ^ (row & 7))) * 16;
            const __half* src = g_Wh + (size_t)(bn + row) * K_DIM + k0 + c * 8;
            asm volatile("cp.async.cg.shared.global [%0], [%1], 16;"
                         :: "r"(dst), "l"(src) : "memory");
        }
    };

    // ---- compute one K-tile from stage s ----
    auto compute_tile = [&](int s) {
        const uint32_t ab = sbase + s * STAGE_BYTES;
        const uint32_t bb = ab + A_STAGE_BYTES;
#pragma unroll
        for (int kk = 0; kk < 4; kk++) {          // 4 x k16
            // A fragments: 4 x ldmatrix.x4 (16x16 each)
            uint32_t a[4][4];
#pragma unroll
            for (int mi = 0; mi < 4; mi++) {
                const int r = wm * 64 + mi * 16 + (quad & 1) * 8 + lrow;
                const int c = 2 * kk + (quad >> 1);
                ldsm_x4(a[mi][0], a[mi][1], a[mi][2], a[mi][3],
                        ab + ((r << 3) + (c ^ (r & 7))) * 16);
            }
            // B fragments: 4 x ldmatrix.x4, each covers 2 ni
#pragma unroll
            for (int np = 0; np < 4; np++) {
                const int n = wn * 64 + np * 16 + (quad >> 1) * 8 + lrow;
                const int c = 2 * kk + (quad & 1);
                uint32_t b0, b1, b2, b3;
                ldsm_x4(b0, b1, b2, b3, bb + ((n << 3) + (c ^ (n & 7))) * 16);
#pragma unroll
                for (int mi = 0; mi < 4; mi++) {
                    asm volatile(
                        "mma.sync.aligned.m16n8k16.row.col.f32.f16.f16.f32 "
                        "{%0,%1,%2,%3}, {%4,%5,%6,%7}, {%8,%9}, {%0,%1,%2,%3};"
                        : "+f"(acc[mi][2*np][0]), "+f"(acc[mi][2*np][1]),
                          "+f"(acc[mi][2*np][2]), "+f"(acc[mi][2*np][3])
                        : "r"(a[mi][0]), "r"(a[mi][1]), "r"(a[mi][2]), "r"(a[mi][3]),
                          "r"(b0), "r"(b1));
                    asm volatile(
                        "mma.sync.aligned.m16n8k16.row.col.f32.f16.f16.f32 "
                        "{%0,%1,%2,%3}, {%4,%5,%6,%7}, {%8,%9}, {%0,%1,%2,%3};"
                        : "+f"(acc[mi][2*np+1][0]), "+f"(acc[mi][2*np+1][1]),
                          "+f"(acc[mi][2*np+1][2]), "+f"(acc[mi][2*np+1][3])
                        : "r"(a[mi][0]), "r"(a[mi][1]), "r"(a[mi][2]), "r"(a[mi][3]),
                          "r"(b2), "r"(b3));
                }
            }
        }
    };

    // ---- prologue: stages 0..2 ----
#pragma unroll
    for (int s = 0; s < STAGES - 1; s++) {
        load_tile(s, s);
        asm volatile("cp.async.commit_group;" ::: "memory");
    }

    // ---- mainloop ----
#pragma unroll 1
    for (int t = 0; t < KTILES; t++) {
        asm volatile("cp.async.wait_group %0;" :: "n"(STAGES - 2) : "memory");
        __syncthreads();
        compute_tile(t & (STAGES - 1));
        if (t + STAGES - 1 < KTILES)
            load_tile((t + STAGES - 1) & (STAGES - 1), t + STAGES - 1);
        asm volatile("cp.async.commit_group;" ::: "memory");
    }

    // ---- epilogue: fp32 writes ----
#pragma unroll
    for (int mi = 0; mi < 4; mi++) {
#pragma unroll
        for (int ni = 0; ni < 8; ni++) {
            const int row = bm + wm * 64 + mi * 16 + g;
            const int col = bn + wn * 64 + ni * 8 + tg * 2;
            *(float2*)(y + (size_t)row       * N_DIM + col) =
                make_float2(acc[mi][ni][0], acc[mi][ni][1]);
            *(float2*)(y + (size_t)(row + 8) * N_DIM + col) =
                make_float2(acc[mi][ni][2], acc[mi][ni][3]);
        }
    }
}

// ---------------------------------------------------------------------------
// Kernel 4: in-place RMSNorm over rows of 1024, times norm_w.
// ---------------------------------------------------------------------------
__global__ void rmsnorm_kernel(float* __restrict__ y, const float* __restrict__ nw) {
    __shared__ float red[8];
    const int row = blockIdx.x;
    const int tid = threadIdx.x;
    float4* p = (float4*)(y + (size_t)row * H_DIM);

    float4 v = p[tid];
    float ss = v.x * v.x + v.y * v.y + v.z * v.z + v.w * v.w;
#pragma unroll
    for (int o = 16; o; o >>= 1) ss += __shfl_xor_sync(0xFFFFFFFFu, ss, o);
    if ((tid & 31) == 0) red[tid >> 5] = ss;
    __syncthreads();
    if (tid < 32) {
        float s = (tid < 8) ? red[tid] : 0.f;
#pragma unroll
        for (int o = 4; o; o >>= 1) s += __shfl_xor_sync(0xFFFFFFFFu, s, o);
        if (tid == 0) red[0] = s;
    }
    __syncthreads();

    const float scale = rsqrtf(red[0] * (1.0f / H_DIM) + EPS);
    float4 w = ((const float4*)nw)[tid];
    v.x *= scale * w.x;
    v.y *= scale * w.y;
    v.z *= scale * w.z;
    v.w *= scale * w.w;
    p[tid] = v;
}

// ---------------------------------------------------------------------------
extern "C" void kernel_launch(void* const* d_in, const int* in_sizes, int n_in,
                              void* d_out, int out_size) {
    const float* x      = (const float*)d_in[0];
    const float* conv_w = (const float*)d_in[1];
    const float* norm_w = (const float*)d_in[2];
    float* out = (float*)d_out;

    cudaFuncSetAttribute(gemm_f16_kernel,
                         cudaFuncAttributeMaxDynamicSharedMemorySize, SMEM_BYTES);

    prep_w_kernel<<<(H_DIM * H_DIM) / (256 * 4), 256>>>(conv_w);
    prep_x_kernel<<<(int)(((size_t)M_TOTAL * K_DIM) / (256 * 4)), 256>>>(x);

    dim3 grid(N_DIM / BN, M_TOTAL / BM);   // 4 x 128 = 512 CTAs
    gemm_f16_kernel<<<grid, NTHREADS, SMEM_BYTES>>>(out);

    rmsnorm_kernel<<<M_TOTAL, 256>>>(out, norm_w);
}

// round 8
// speedup vs baseline: 2.0864x; 1.0411x over previous
#include <cuda_runtime.h>
#include <cuda_fp16.h>
#include <cstdint>

// Problem shape (fixed): x[B=4,S=4096,H=1024], conv_w[L=20,H,H], norm_w[H]
#define H_DIM   1024
#define L_DIM   20
#define M_TOTAL 16384
#define K_DIM   1024
#define N_DIM   1024
#define EPS     1e-6f

// ---- GEMM config ----
#define BM 128
#define BN 256
#define BKH 64                      // K-tile in halfs (128 B/row)
#define KTILES (K_DIM / BKH)        // 16
#define STAGES 4
#define A_STAGE_BYTES (BM * 128)    // 16384
#define B_STAGE_BYTES (BN * 128)    // 32768
#define STAGE_BYTES (A_STAGE_BYTES + B_STAGE_BYTES)   // 49152
#define SMEM_BYTES (STAGES * STAGE_BYTES)             // 196608
#define NTHREADS 256

// fp16 scratch (device globals — allocation-free)
__device__ __half g_Wh[N_DIM * K_DIM];            // 2 MB
__device__ __half g_Xh[(size_t)M_TOTAL * K_DIM];  // 32 MB

// ---------------------------------------------------------------------------
// Kernel 1: W[o,i] = (1/L) * sum_l conv_w[l,o,i]  -> fp16
// 8 elements/thread, two interleaved accumulator chains for MLP.
// ---------------------------------------------------------------------------
__global__ void prep_w_kernel(const float* __restrict__ conv_w) {
    int idx = (blockIdx.x * blockDim.x + threadIdx.x) * 8;
    const float inv = 1.0f / (float)L_DIM;
    float4 a0 = make_float4(0.f, 0.f, 0.f, 0.f);
    float4 a1 = make_float4(0.f, 0.f, 0.f, 0.f);
#pragma unroll
    for (int l = 0; l < L_DIM; l++) {
        const float* p = conv_w + (size_t)l * H_DIM * H_DIM + idx;
        float4 v0 = *(const float4*)(p);
        float4 v1 = *(const float4*)(p + 4);
        a0.x += v0.x; a0.y += v0.y; a0.z += v0.z; a0.w += v0.w;
        a1.x += v1.x; a1.y += v1.y; a1.z += v1.z; a1.w += v1.w;
    }
    __half2 h0 = __floats2half2_rn(a0.x * inv, a0.y * inv);
    __half2 h1 = __floats2half2_rn(a0.z * inv, a0.w * inv);
    __half2 h2 = __floats2half2_rn(a1.x * inv, a1.y * inv);
    __half2 h3 = __floats2half2_rn(a1.z * inv, a1.w * inv);
    *(uint4*)(g_Wh + idx) = make_uint4(*(uint32_t*)&h0, *(uint32_t*)&h1,
                                       *(uint32_t*)&h2, *(uint32_t*)&h3);
}

// ---------------------------------------------------------------------------
// Kernel 2: x (fp32) -> g_Xh (fp16), 8 elems/thread
// ---------------------------------------------------------------------------
__global__ void prep_x_kernel(const float* __restrict__ x) {
    size_t idx = ((size_t)blockIdx.x * blockDim.x + threadIdx.x) * 8;
    float4 v0 = *(const float4*)(x + idx);
    float4 v1 = *(const float4*)(x + idx + 4);
    __half2 h0 = __floats2half2_rn(v0.x, v0.y);
    __half2 h1 = __floats2half2_rn(v0.z, v0.w);
    __half2 h2 = __floats2half2_rn(v1.x, v1.y);
    __half2 h3 = __floats2half2_rn(v1.z, v1.w);
    *(uint4*)(g_Xh + idx) = make_uint4(*(uint32_t*)&h0, *(uint32_t*)&h1,
                                       *(uint32_t*)&h2, *(uint32_t*)&h3);
}

// ---------------------------------------------------------------------------
// Kernel 3: y = x @ W^T  (fp16 mma.sync m16n8k16, fp32 accum)
// CTA 128x256xK64, 8 warps = 2(m) x 4(n), warp tile 64x64.
// 4-stage cp.async pipeline; next-tile loads interleaved into the kk loop.
// ---------------------------------------------------------------------------
__device__ __forceinline__ uint32_t smem_u32(const void* p) {
    uint32_t a;
    asm("{ .reg .u64 t; cvta.to.shared.u64 t, %1; cvt.u32.u64 %0, t; }" : "=r"(a) : "l"(p));
    return a;
}
__device__ __forceinline__ void ldsm_x4(uint32_t& r0, uint32_t& r1, uint32_t& r2, uint32_t& r3,
                                        uint32_t addr) {
    asm volatile("ldmatrix.sync.aligned.m8n8.x4.shared.b16 {%0,%1,%2,%3}, [%4];"
                 : "=r"(r0), "=r"(r1), "=r"(r2), "=r"(r3) : "r"(addr));
}

__global__ __launch_bounds__(NTHREADS, 1)
void gemm_f16_kernel(float* __restrict__ y) {
    extern __shared__ char smem[];
    const uint32_t sbase = smem_u32(smem);

    const int tid  = threadIdx.x;
    const int warp = tid >> 5;
    const int lane = tid & 31;
    const int wm   = warp >> 2;
    const int wn   = warp & 3;
    const int g    = lane >> 2;
    const int tg   = lane & 3;
    const int quad = lane >> 3;
    const int lrow = lane & 7;

    const int bm = blockIdx.y * BM;
    const int bn = blockIdx.x * BN;

    // precomputed per-thread load coordinates
    const int arow = tid >> 3, ac = tid & 7;     // + i*32 rows, 4 iters
    const uint32_t a_soff = (uint32_t)(((arow << 3) + (ac ^ (arow & 7))) * 16);

    float acc[4][8][4];
#pragma unroll
    for (int mi = 0; mi < 4; mi++)
#pragma unroll
        for (int ni = 0; ni < 8; ni++)
#pragma unroll
            for (int c = 0; c < 4; c++) acc[mi][ni][c] = 0.f;

    // ---- A loads (4 chunks) for tile t into stage s ----
    auto load_A = [&](int s, int t) {
        const uint32_t ab = sbase + s * STAGE_BYTES;
        const int k0 = t * BKH;
#pragma unroll
        for (int i = 0; i < 4; i++) {
            const int row = arow + i * 32;
            const uint32_t dst = ab + a_soff + (uint32_t)(i * 32 * 128);
            const __half* src = g_Xh + (size_t)(bm + row) * K_DIM + k0 + ac * 8;
            asm volatile("cp.async.cg.shared.global [%0], [%1], 16;"
                         :: "r"(dst), "l"(src) : "memory");
        }
    };
    // ---- B loads, half h (4 chunks each) ----
    auto load_B = [&](int s, int t, int h) {
        const uint32_t bb = sbase + s * STAGE_BYTES + A_STAGE_BYTES;
        const int k0 = t * BKH;
#pragma unroll
        for (int i = 0; i < 4; i++) {
            const int row = arow + (h * 4 + i) * 32;
            const uint32_t dst = bb + a_soff + (uint32_t)((h * 4 + i) * 32 * 128);
            const __half* src = g_Wh + (size_t)(bn + row) * K_DIM + k0 + ac * 8;
            asm volatile("cp.async.cg.shared.global [%0], [%1], 16;"
                         :: "r"(dst), "l"(src) : "memory");
        }
    };
    auto load_full = [&](int s, int t) {
        load_A(s, t); load_B(s, t, 0); load_B(s, t, 1);
    };

    // ---- compute tile in stage s, interleaving loads for tile tl/stage sl ----
    auto compute_tile = [&](int s, int sl, int tl, bool do_load) {
        const uint32_t ab = sbase + s * STAGE_BYTES;
        const uint32_t bb = ab + A_STAGE_BYTES;
#pragma unroll
        for (int kk = 0; kk < 4; kk++) {
            if (do_load) {                 // spread 12 cp.async across kk 0..2
                if (kk == 0) load_A(sl, tl);
                else if (kk == 1) load_B(sl, tl, 0);
                else if (kk == 2) load_B(sl, tl, 1);
            }
            uint32_t a[4][4];
#pragma unroll
            for (int mi = 0; mi < 4; mi++) {
                const int r = wm * 64 + mi * 16 + (quad & 1) * 8 + lrow;
                const int c = 2 * kk + (quad >> 1);
                ldsm_x4(a[mi][0], a[mi][1], a[mi][2], a[mi][3],
                        ab + ((r << 3) + (c ^ (r & 7))) * 16);
            }
#pragma unroll
            for (int np = 0; np < 4; np++) {
                const int n = wn * 64 + np * 16 + (quad >> 1) * 8 + lrow;
                const int c = 2 * kk + (quad & 1);
                uint32_t b0, b1, b2, b3;
                ldsm_x4(b0, b1, b2, b3, bb + ((n << 3) + (c ^ (n & 7))) * 16);
#pragma unroll
                for (int mi = 0; mi < 4; mi++) {
                    asm volatile(
                        "mma.sync.aligned.m16n8k16.row.col.f32.f16.f16.f32 "
                        "{%0,%1,%2,%3}, {%4,%5,%6,%7}, {%8,%9}, {%0,%1,%2,%3};"
                        : "+f"(acc[mi][2*np][0]), "+f"(acc[mi][2*np][1]),
                          "+f"(acc[mi][2*np][2]), "+f"(acc[mi][2*np][3])
                        : "r"(a[mi][0]), "r"(a[mi][1]), "r"(a[mi][2]), "r"(a[mi][3]),
                          "r"(b0), "r"(b1));
                    asm volatile(
                        "mma.sync.aligned.m16n8k16.row.col.f32.f16.f16.f32 "
                        "{%0,%1,%2,%3}, {%4,%5,%6,%7}, {%8,%9}, {%0,%1,%2,%3};"
                        : "+f"(acc[mi][2*np+1][0]), "+f"(acc[mi][2*np+1][1]),
                          "+f"(acc[mi][2*np+1][2]), "+f"(acc[mi][2*np+1][3])
                        : "r"(a[mi][0]), "r"(a[mi][1]), "r"(a[mi][2]), "r"(a[mi][3]),
                          "r"(b2), "r"(b3));
                }
            }
        }
    };

    // ---- prologue: stages 0..2 ----
#pragma unroll
    for (int s = 0; s < STAGES - 1; s++) {
        load_full(s, s);
        asm volatile("cp.async.commit_group;" ::: "memory");
    }

    // ---- mainloop ----
#pragma unroll 1
    for (int t = 0; t < KTILES; t++) {
        asm volatile("cp.async.wait_group %0;" :: "n"(STAGES - 2) : "memory");
        __syncthreads();
        const bool dl = (t + STAGES - 1 < KTILES);
        compute_tile(t & (STAGES - 1), (t + STAGES - 1) & (STAGES - 1),
                     t + STAGES - 1, dl);
        asm volatile("cp.async.commit_group;" ::: "memory");
    }

    // ---- epilogue ----
#pragma unroll
    for (int mi = 0; mi < 4; mi++) {
#pragma unroll
        for (int ni = 0; ni < 8; ni++) {
            const int row = bm + wm * 64 + mi * 16 + g;
            const int col = bn + wn * 64 + ni * 8 + tg * 2;
            *(float2*)(y + (size_t)row       * N_DIM + col) =
                make_float2(acc[mi][ni][0], acc[mi][ni][1]);
            *(float2*)(y + (size_t)(row + 8) * N_DIM + col) =
                make_float2(acc[mi][ni][2], acc[mi][ni][3]);
        }
    }
}

// ---------------------------------------------------------------------------
// Kernel 4: in-place RMSNorm, warp-per-row (no smem, no block sync).
// 256 threads = 8 warps = 8 rows per CTA; 8 float4 per lane.
// ---------------------------------------------------------------------------
__global__ __launch_bounds__(256)
void rmsnorm_kernel(float* __restrict__ y, const float* __restrict__ nw) {
    const int warp = threadIdx.x >> 5;
    const int lane = threadIdx.x & 31;
    const size_t row = (size_t)blockIdx.x * 8 + warp;
    float4* p = (float4*)(y + row * H_DIM);
    const float4* w = (const float4*)nw;

    float4 v[8];
    float ss = 0.f;
#pragma unroll
    for (int i = 0; i < 8; i++) {
        v[i] = p[lane + i * 32];
        ss += v[i].x * v[i].x + v[i].y * v[i].y + v[i].z * v[i].z + v[i].w * v[i].w;
    }
#pragma unroll
    for (int o = 16; o; o >>= 1) ss += __shfl_xor_sync(0xFFFFFFFFu, ss, o);

    const float scale = rsqrtf(ss * (1.0f / H_DIM) + EPS);
#pragma unroll
    for (int i = 0; i < 8; i++) {
        float4 ww = w[lane + i * 32];
        v[i].x *= scale * ww.x;
        v[i].y *= scale * ww.y;
        v[i].z *= scale * ww.z;
        v[i].w *= scale * ww.w;
        p[lane + i * 32] = v[i];
    }
}

// ---------------------------------------------------------------------------
extern "C" void kernel_launch(void* const* d_in, const int* in_sizes, int n_in,
                              void* d_out, int out_size) {
    const float* x      = (const float*)d_in[0];
    const float* conv_w = (const float*)d_in[1];
    const float* norm_w = (const float*)d_in[2];
    float* out = (float*)d_out;

    cudaFuncSetAttribute(gemm_f16_kernel,
                         cudaFuncAttributeMaxDynamicSharedMemorySize, SMEM_BYTES);

    prep_w_kernel<<<(H_DIM * H_DIM) / (256 * 8), 256>>>(conv_w);
    prep_x_kernel<<<(int)(((size_t)M_TOTAL * K_DIM) / (256 * 8)), 256>>>(x);

    dim3 grid(N_DIM / BN, M_TOTAL / BM);   // 4 x 128 = 512 CTAs
    gemm_f16_kernel<<<grid, NTHREADS, SMEM_BYTES>>>(out);

    rmsnorm_kernel<<<M_TOTAL / 8, 256>>>(out, norm_w);
}

// round 9
// speedup vs baseline: 2.2705x; 1.0882x over previous
#include <cuda_runtime.h>
#include <cuda_fp16.h>
#include <cstdint>

// Problem shape (fixed): x[B=4,S=4096,H=1024], conv_w[L=20,H,H], norm_w[H]
#define H_DIM   1024
#define L_DIM   20
#define M_TOTAL 16384
#define K_DIM   1024
#define N_DIM   1024
#define EPS     1e-6f

// ---- GEMM config ----
#define BM 128
#define BN 128
#define BKH 64                       // K-tile in halfs (128 B/row)
#define KTILES (K_DIM / BKH)         // 16
#define STAGES 3
#define A_STAGE_BYTES (BM * 128)     // 16384
#define B_STAGE_BYTES (BN * 128)     // 16384
#define STAGE_BYTES (A_STAGE_BYTES + B_STAGE_BYTES)   // 32768
#define SMEM_BYTES (STAGES * STAGE_BYTES)             // 98304 -> 2 CTAs/SM
#define NTHREADS 256

// fp16 scratch (device globals — allocation-free)
__device__ __half g_Wh[N_DIM * K_DIM];            // 2 MB
__device__ __half g_Xh[(size_t)M_TOTAL * K_DIM];  // 32 MB
__device__ __half g_Yh[(size_t)M_TOTAL * N_DIM];  // 32 MB (GEMM out, pre-norm)

#define PREP_W_BLOCKS ((H_DIM * H_DIM) / (256 * 8))                    // 512
#define PREP_X_BLOCKS ((int)(((size_t)M_TOTAL * K_DIM) / (256 * 8)))   // 8192

// ---------------------------------------------------------------------------
// Kernel 1 (fused prep): blocks [0,512) average conv_w -> g_Wh;
// blocks [512, 512+8192) convert x -> g_Xh. Both DRAM streams overlap.
// ---------------------------------------------------------------------------
__global__ void prep_kernel(const float* __restrict__ x,
                            const float* __restrict__ conv_w) {
    if (blockIdx.x < PREP_W_BLOCKS) {
        int idx = (blockIdx.x * blockDim.x + threadIdx.x) * 8;
        const float inv = 1.0f / (float)L_DIM;
        float4 a0 = make_float4(0.f, 0.f, 0.f, 0.f);
        float4 a1 = make_float4(0.f, 0.f, 0.f, 0.f);
#pragma unroll
        for (int l = 0; l < L_DIM; l++) {
            const float* p = conv_w + (size_t)l * H_DIM * H_DIM + idx;
            float4 v0 = *(const float4*)(p);
            float4 v1 = *(const float4*)(p + 4);
            a0.x += v0.x; a0.y += v0.y; a0.z += v0.z; a0.w += v0.w;
            a1.x += v1.x; a1.y += v1.y; a1.z += v1.z; a1.w += v1.w;
        }
        __half2 h0 = __floats2half2_rn(a0.x * inv, a0.y * inv);
        __half2 h1 = __floats2half2_rn(a0.z * inv, a0.w * inv);
        __half2 h2 = __floats2half2_rn(a1.x * inv, a1.y * inv);
        __half2 h3 = __floats2half2_rn(a1.z * inv, a1.w * inv);
        *(uint4*)(g_Wh + idx) = make_uint4(*(uint32_t*)&h0, *(uint32_t*)&h1,
                                           *(uint32_t*)&h2, *(uint32_t*)&h3);
    } else {
        size_t idx = ((size_t)(blockIdx.x - PREP_W_BLOCKS) * blockDim.x + threadIdx.x) * 8;
        float4 v0 = *(const float4*)(x + idx);
        float4 v1 = *(const float4*)(x + idx + 4);
        __half2 h0 = __floats2half2_rn(v0.x, v0.y);
        __half2 h1 = __floats2half2_rn(v0.z, v0.w);
        __half2 h2 = __floats2half2_rn(v1.x, v1.y);
        __half2 h3 = __floats2half2_rn(v1.z, v1.w);
        *(uint4*)(g_Xh + idx) = make_uint4(*(uint32_t*)&h0, *(uint32_t*)&h1,
                                           *(uint32_t*)&h2, *(uint32_t*)&h3);
    }
}

// ---------------------------------------------------------------------------
// Kernel 2: y = x @ W^T  (fp16 mma.sync m16n8k16, fp32 accum) -> g_Yh (fp16)
// CTA 128x128xK64, 8 warps = 2(m) x 4(n), warp tile 64x32.
// 3-stage cp.async pipeline, 2 CTAs/SM. Loads interleaved into kk loop.
// ---------------------------------------------------------------------------
__device__ __forceinline__ uint32_t smem_u32(const void* p) {
    uint32_t a;
    asm("{ .reg .u64 t; cvta.to.shared.u64 t, %1; cvt.u32.u64 %0, t; }" : "=r"(a) : "l"(p));
    return a;
}
__device__ __forceinline__ void ldsm_x4(uint32_t& r0, uint32_t& r1, uint32_t& r2, uint32_t& r3,
                                        uint32_t addr) {
    asm volatile("ldmatrix.sync.aligned.m8n8.x4.shared.b16 {%0,%1,%2,%3}, [%4];"
                 : "=r"(r0), "=r"(r1), "=r"(r2), "=r"(r3) : "r"(addr));
}

__global__ __launch_bounds__(NTHREADS, 2)
void gemm_f16_kernel() {
    extern __shared__ char smem[];
    const uint32_t sbase = smem_u32(smem);

    const int tid  = threadIdx.x;
    const int warp = tid >> 5;
    const int lane = tid & 31;
    const int wm   = warp >> 2;          // 0..1 -> m offset wm*64
    const int wn   = warp & 3;           // 0..3 -> n offset wn*32
    const int g    = lane >> 2;
    const int tg   = lane & 3;
    const int quad = lane >> 3;
    const int lrow = lane & 7;

    const int bm = blockIdx.y * BM;
    const int bn = blockIdx.x * BN;

    const int arow = tid >> 3, ac = tid & 7;    // 512 of 1024 chunks; +i*32 rows
    const uint32_t soff = (uint32_t)(((arow << 3) + (ac ^ (arow & 7))) * 16);

    float acc[4][4][4];
#pragma unroll
    for (int mi = 0; mi < 4; mi++)
#pragma unroll
        for (int ni = 0; ni < 4; ni++)
#pragma unroll
            for (int c = 0; c < 4; c++) acc[mi][ni][c] = 0.f;

    auto load_A = [&](int s, int t) {
        const uint32_t ab = sbase + s * STAGE_BYTES;
        const int k0 = t * BKH;
#pragma unroll
        for (int i = 0; i < 4; i++) {
            const uint32_t dst = ab + soff + (uint32_t)(i * 32 * 128);
            const __half* src = g_Xh + (size_t)(bm + arow + i * 32) * K_DIM + k0 + ac * 8;
            asm volatile("cp.async.cg.shared.global [%0], [%1], 16;"
                         :: "r"(dst), "l"(src) : "memory");
        }
    };
    auto load_B = [&](int s, int t) {
        const uint32_t bb = sbase + s * STAGE_BYTES + A_STAGE_BYTES;
        const int k0 = t * BKH;
#pragma unroll
        for (int i = 0; i < 4; i++) {
            const uint32_t dst = bb + soff + (uint32_t)(i * 32 * 128);
            const __half* src = g_Wh + (size_t)(bn + arow + i * 32) * K_DIM + k0 + ac * 8;
            asm volatile("cp.async.cg.shared.global [%0], [%1], 16;"
                         :: "r"(dst), "l"(src) : "memory");
        }
    };

    auto compute_tile = [&](int s, int sl, int tl, bool do_load) {
        const uint32_t ab = sbase + s * STAGE_BYTES;
        const uint32_t bb = ab + A_STAGE_BYTES;
#pragma unroll
        for (int kk = 0; kk < 4; kk++) {
            if (do_load) {
                if (kk == 0) load_A(sl, tl);
                else if (kk == 1) load_B(sl, tl);
            }
            uint32_t a[4][4];
#pragma unroll
            for (int mi = 0; mi < 4; mi++) {
                const int r = wm * 64 + mi * 16 + (quad & 1) * 8 + lrow;
                const int c = 2 * kk + (quad >> 1);
                ldsm_x4(a[mi][0], a[mi][1], a[mi][2], a[mi][3],
                        ab + ((r << 3) + (c ^ (r & 7))) * 16);
            }
#pragma unroll
            for (int np = 0; np < 2; np++) {
                const int n = wn * 32 + np * 16 + (quad >> 1) * 8 + lrow;
                const int c = 2 * kk + (quad & 1);
                uint32_t b0, b1, b2, b3;
                ldsm_x4(b0, b1, b2, b3, bb + ((n << 3) + (c ^ (n & 7))) * 16);
#pragma unroll
                for (int mi = 0; mi < 4; mi++) {
                    asm volatile(
                        "mma.sync.aligned.m16n8k16.row.col.f32.f16.f16.f32 "
                        "{%0,%1,%2,%3}, {%4,%5,%6,%7}, {%8,%9}, {%0,%1,%2,%3};"
                        : "+f"(acc[mi][2*np][0]), "+f"(acc[mi][2*np][1]),
                          "+f"(acc[mi][2*np][2]), "+f"(acc[mi][2*np][3])
                        : "r"(a[mi][0]), "r"(a[mi][1]), "r"(a[mi][2]), "r"(a[mi][3]),
                          "r"(b0), "r"(b1));
                    asm volatile(
                        "mma.sync.aligned.m16n8k16.row.col.f32.f16.f16.f32 "
                        "{%0,%1,%2,%3}, {%4,%5,%6,%7}, {%8,%9}, {%0,%1,%2,%3};"
                        : "+f"(acc[mi][2*np+1][0]), "+f"(acc[mi][2*np+1][1]),
                          "+f"(acc[mi][2*np+1][2]), "+f"(acc[mi][2*np+1][3])
                        : "r"(a[mi][0]), "r"(a[mi][1]), "r"(a[mi][2]), "r"(a[mi][3]),
                          "r"(b2), "r"(b3));
                }
            }
        }
    };

    // ---- prologue: stages 0,1 ----
#pragma unroll
    for (int s = 0; s < STAGES - 1; s++) {
        load_A(s, s); load_B(s, s);
        asm volatile("cp.async.commit_group;" ::: "memory");
    }

    // ---- mainloop ----
    int cs = 0, ls = STAGES - 1;
#pragma unroll 1
    for (int t = 0; t < KTILES; t++) {
        asm volatile("cp.async.wait_group %0;" :: "n"(STAGES - 2) : "memory");
        __syncthreads();
        compute_tile(cs, ls, t + STAGES - 1, t + STAGES - 1 < KTILES);
        asm volatile("cp.async.commit_group;" ::: "memory");
        if (++cs == STAGES) cs = 0;
        if (++ls == STAGES) ls = 0;
    }

    // ---- epilogue: fp16 stores to g_Yh ----
#pragma unroll
    for (int mi = 0; mi < 4; mi++) {
#pragma unroll
        for (int ni = 0; ni < 4; ni++) {
            const int row = bm + wm * 64 + mi * 16 + g;
            const int col = bn + wn * 32 + ni * 8 + tg * 2;
            __half2 h01 = __floats2half2_rn(acc[mi][ni][0], acc[mi][ni][1]);
            __half2 h23 = __floats2half2_rn(acc[mi][ni][2], acc[mi][ni][3]);
            *(uint32_t*)(g_Yh + (size_t)row       * N_DIM + col) = *(uint32_t*)&h01;
            *(uint32_t*)(g_Yh + (size_t)(row + 8) * N_DIM + col) = *(uint32_t*)&h23;
        }
    }
}

// ---------------------------------------------------------------------------
// Kernel 3: RMSNorm g_Yh (fp16) -> out (fp32), warp-per-row.
// 8 warps/CTA; each lane handles 32 halfs (4 x uint4 = 4 x 8 halfs).
// ---------------------------------------------------------------------------
__global__ __launch_bounds__(256)
void rmsnorm_kernel(float* __restrict__ out, const float* __restrict__ nw) {
    const int warp = threadIdx.x >> 5;
    const int lane = threadIdx.x & 31;
    const size_t row = (size_t)blockIdx.x * 8 + warp;
    const uint4* p = (const uint4*)(g_Yh + row * H_DIM);   // 128 uint4 per row
    float* o = out + row * H_DIM;

    float2 f[4][4];   // [i][j] = halfs (lane*8 + i*256 + 2j, +1)
    float ss = 0.f;
#pragma unroll
    for (int i = 0; i < 4; i++) {
        uint4 h = p[lane + i * 32];
        f[i][0] = __half22float2(*(__half2*)&h.x);
        f[i][1] = __half22float2(*(__half2*)&h.y);
        f[i][2] = __half22float2(*(__half2*)&h.z);
        f[i][3] = __half22float2(*(__half2*)&h.w);
#pragma unroll
        for (int j = 0; j < 4; j++)
            ss += f[i][j].x * f[i][j].x + f[i][j].y * f[i][j].y;
    }
#pragma unroll
    for (int of = 16; of; of >>= 1) ss += __shfl_xor_sync(0xFFFFFFFFu, ss, of);

    const float scale = rsqrtf(ss * (1.0f / H_DIM) + EPS);
#pragma unroll
    for (int i = 0; i < 4; i++) {
        const int base = lane * 8 + i * 256;
        float4 w0 = *(const float4*)(nw + base);
        float4 w1 = *(const float4*)(nw + base + 4);
        float4 o0, o1;
        o0.x = f[i][0].x * scale * w0.x;
        o0.y = f[i][0].y * scale * w0.y;
        o0.z = f[i][1].x * scale * w0.z;
        o0.w = f[i][1].y * scale * w0.w;
        o1.x = f[i][2].x * scale * w1.x;
        o1.y = f[i][2].y * scale * w1.y;
        o1.z = f[i][3].x * scale * w1.z;
        o1.w = f[i][3].y * scale * w1.w;
        *(float4*)(o + base)     = o0;
        *(float4*)(o + base + 4) = o1;
    }
}

// ---------------------------------------------------------------------------
extern "C" void kernel_launch(void* const* d_in, const int* in_sizes, int n_in,
                              void* d_out, int out_size) {
    const float* x      = (const float*)d_in[0];
    const float* conv_w = (const float*)d_in[1];
    const float* norm_w = (const float*)d_in[2];
    float* out = (float*)d_out;

    cudaFuncSetAttribute(gemm_f16_kernel,
                         cudaFuncAttributeMaxDynamicSharedMemorySize, SMEM_BYTES);

    prep_kernel<<<PREP_W_BLOCKS + PREP_X_BLOCKS, 256>>>(x, conv_w);

    dim3 grid(N_DIM / BN, M_TOTAL / BM);   // 8 x 128 = 1024 CTAs, 2/SM
    gemm_f16_kernel<<<grid, NTHREADS, SMEM_BYTES>>>();

    rmsnorm_kernel<<<M_TOTAL / 8, 256>>>(out, norm_w);
}